// round 16
// baseline (speedup 1.0000x reference)
#include <cuda_runtime.h>
#include <cuda_bf16.h>
#include <cstdint>

#define BB 64
#define VV 2000
#define DD 16
#define CI 64
#define CO 64
#define VHALF 1000
#define VTILE 128
#define WVB 36

// ---------------- scratch ----------------
__device__ float g_partG[32 * 512];
__device__ float g_inv_norm;
__device__ float g_Zre[2 * BB * DD * CI];
__device__ float g_Zim[2 * BB * DD * CI];
__device__ float2 g_y[(size_t)BB * VV * CI];
__device__ float4 g_AC4[(size_t)VV * CI * CO];   // (Ar, Ai, Cr, Ci)

// ================ K1: gram_partial + z (unchanged, proven) ================
__global__ void __launch_bounds__(256) k1_gram_z(const float* __restrict__ x,
                                                 const float* __restrict__ ner,
                                                 const float* __restrict__ nei) {
    __shared__ float xs[VTILE * 64];
    __shared__ float2 ns[VTILE * 16];
    if (blockIdx.x < 32) {
        float* sr = xs;
        float* si = xs + 1024;
        int blk = blockIdx.x;
        int v0 = blk * 63;
        int cnt = min(63, VV - v0);
        for (int t = threadIdx.x; t < cnt * 16; t += 256) {
            sr[t] = ner[v0 * 16 + t];
            si[t] = nei[v0 * 16 + t];
        }
        __syncthreads();
        int d = threadIdx.x >> 4, e = threadIdx.x & 15;
        float ar = 0.f, ai = 0.f;
        for (int vv = 0; vv < cnt; vv++) {
            float a = sr[vv * 16 + d], b = si[vv * 16 + d];
            float c = sr[vv * 16 + e], dd = si[vv * 16 + e];
            ar += a * c + b * dd;
            ai += a * dd - b * c;
        }
        g_partG[blk * 512 + threadIdx.x * 2]     = ar;
        g_partG[blk * 512 + threadIdx.x * 2 + 1] = ai;
    } else {
        int bx = blockIdx.x - 32;
        int b = bx >> 1;
        int half = bx & 1;
        int vbase = half * VHALF;
        int ig = threadIdx.x & 63;
        int dg = threadIdx.x >> 6;
        float ar[4] = {}, ai[4] = {};
        for (int v0 = 0; v0 < VHALF; v0 += VTILE) {
            int cnt = min(VTILE, VHALF - v0);
            __syncthreads();
            {
                const float4* src = (const float4*)(x + (size_t)b * VV * 64 + (size_t)(vbase + v0) * 64);
                float4* dst = (float4*)xs;
                for (int t = threadIdx.x; t < cnt * 16; t += 256) dst[t] = src[t];
            }
            for (int t = threadIdx.x; t < cnt * 16; t += 256) {
                int vv = t >> 4, d = t & 15;
                ns[vv * 16 + d] = make_float2(ner[(vbase + v0 + vv) * 16 + d],
                                              nei[(vbase + v0 + vv) * 16 + d]);
            }
            __syncthreads();
#pragma unroll 4
            for (int vv = 0; vv < cnt; vv++) {
                float xv = xs[vv * 64 + ig];
                float2 n0 = ns[vv * 16 + dg * 4 + 0];
                float2 n1 = ns[vv * 16 + dg * 4 + 1];
                float2 n2 = ns[vv * 16 + dg * 4 + 2];
                float2 n3 = ns[vv * 16 + dg * 4 + 3];
                ar[0] += n0.x * xv; ai[0] -= n0.y * xv;
                ar[1] += n1.x * xv; ai[1] -= n1.y * xv;
                ar[2] += n2.x * xv; ai[2] -= n2.y * xv;
                ar[3] += n3.x * xv; ai[3] -= n3.y * xv;
            }
        }
#pragma unroll
        for (int k = 0; k < 4; k++) {
            int idx = ((half * BB + b) * 16 + dg * 4 + k) * 64 + ig;
            g_Zre[idx] = ar[k];
            g_Zim[idx] = ai[k];
        }
    }
}

// ================ K2: gram_reduce + y (unchanged) ================
__global__ void __launch_bounds__(256) k2_reduce_y(const float* __restrict__ ner,
                                                   const float* __restrict__ nei) {
    __shared__ float sm[4096];
    if (blockIdx.x == 0) {
        float* red = sm;
        int t = threadIdx.x;
        float gr = 0.f, gi = 0.f;
        for (int blk = 0; blk < 32; blk++) {
            gr += g_partG[blk * 512 + t * 2];
            gi += g_partG[blk * 512 + t * 2 + 1];
        }
        red[t] = gr * gr + gi * gi;
        __syncthreads();
        for (int s = 128; s > 0; s >>= 1) {
            if (t < s) red[t] += red[t + s];
            __syncthreads();
        }
        if (t == 0) g_inv_norm = rsqrtf(red[0]);
    } else {
        float* Zr = sm;
        float* Zi = sm + 1024;
        float* nr = sm + 2048;
        float* ni = sm + 3072;
        int bx = blockIdx.x - 1;
        int b = bx >> 5;
        int v0 = (bx & 31) * 64;
        int vcnt = min(64, VV - v0);
        for (int t = threadIdx.x; t < 1024; t += 256) {
            Zr[t] = g_Zre[b * 1024 + t] + g_Zre[65536 + b * 1024 + t];
            Zi[t] = g_Zim[b * 1024 + t] + g_Zim[65536 + b * 1024 + t];
        }
        for (int t = threadIdx.x; t < vcnt * 16; t += 256) {
            nr[t] = ner[v0 * 16 + t];
            ni[t] = nei[v0 * 16 + t];
        }
        __syncthreads();
        int i = threadIdx.x & 63;
        int vb = threadIdx.x >> 6;
        float zr[16], zi[16];
#pragma unroll
        for (int d = 0; d < 16; d++) { zr[d] = Zr[d * 64 + i]; zi[d] = Zi[d * 64 + i]; }
        for (int vl = vb; vl < vcnt; vl += 4) {
            float yr = 0.f, yi = 0.f;
#pragma unroll
            for (int d = 0; d < 16; d++) {
                float a = nr[vl * 16 + d], c = ni[vl * 16 + d];
                yr += a * zr[d] - c * zi[d];
                yi += a * zi[d] + c * zr[d];
            }
            g_y[(size_t)b * VV * 64 + (size_t)(v0 + vl) * 64 + i] = make_float2(yr, yi);
        }
    }
}

// ================ K3: wcomb (unchanged) ================
__global__ void __launch_bounds__(256) wcomb_kernel(const float* __restrict__ ner,
                                                    const float* __restrict__ nei,
                                                    const float* __restrict__ wr,
                                                    const float* __restrict__ wi) {
    int io2 = blockIdx.x * 256 + threadIdx.x;
    int io = io2 * 2;
    int vstart = blockIdx.y * WVB;
    int vcnt = min(WVB, VV - vstart);
    float s = g_inv_norm;
    float2 P0r[16], P0i[16], P1r[16], P1i[16];
#pragma unroll
    for (int d = 0; d < 16; d++) {
        float2 r0 = *(const float2*)&wr[(d * 3 + 0) * 4096 + io];
        float2 r1 = *(const float2*)&wr[(d * 3 + 1) * 4096 + io];
        float2 r2 = *(const float2*)&wr[(d * 3 + 2) * 4096 + io];
        float2 i0 = *(const float2*)&wi[(d * 3 + 0) * 4096 + io];
        float2 i1 = *(const float2*)&wi[(d * 3 + 1) * 4096 + io];
        float2 i2 = *(const float2*)&wi[(d * 3 + 2) * 4096 + io];
        P0r[d] = make_float2(r0.x - r2.x, r0.y - r2.y);
        P0i[d] = make_float2(i0.x - i2.x, i0.y - i2.y);
        P1r[d] = make_float2((r1.x + 2.f * r2.x) * s, (r1.y + 2.f * r2.y) * s);
        P1i[d] = make_float2((i1.x + 2.f * i2.x) * s, (i1.y + 2.f * i2.y) * s);
    }
    __shared__ float2 nsm[WVB * 16];
    for (int t = threadIdx.x; t < vcnt * 16; t += 256)
        nsm[t] = make_float2(ner[vstart * 16 + t], nei[vstart * 16 + t]);
    __syncthreads();
    for (int vl = 0; vl < vcnt; vl++) {
        float Ar0 = 0.f, Ai0 = 0.f, Cr0 = 0.f, Ci0 = 0.f;
        float Ar1 = 0.f, Ai1 = 0.f, Cr1 = 0.f, Ci1 = 0.f;
#pragma unroll
        for (int d = 0; d < 16; d++) {
            float2 n = nsm[vl * 16 + d];
            float a = n.x, b = n.y;
            Ar0 += a * P0r[d].x - b * P0i[d].x;
            Ai0 += a * P0i[d].x + b * P0r[d].x;
            Cr0 += a * P1r[d].x - b * P1i[d].x;
            Ci0 += a * P1i[d].x + b * P1r[d].x;
            Ar1 += a * P0r[d].y - b * P0i[d].y;
            Ai1 += a * P0i[d].y + b * P0r[d].y;
            Cr1 += a * P1r[d].y - b * P1i[d].y;
            Ci1 += a * P1i[d].y + b * P1r[d].y;
        }
        size_t off = (size_t)(vstart + vl) * 4096 + io;
        g_AC4[off]     = make_float4(Ar0, Ai0, Cr0, Ci0);
        g_AC4[off + 1] = make_float4(Ar1, Ai1, Cr1, Ci1);
    }
}

// ================ K4: HMMA out, full-v blocks, 32m x 32n warps ================
#define SW 100
#define SM_WH 0                       // 128*100*4 = 51200
#define SM_WL 51200
#define SM_XH 102400                  // 64*100*4 = 25600
#define SM_XL 128000
#define SM_BIAS 153600                // 128 floats
#define SM_TOTAL 154112

__device__ __forceinline__ void split_pack(float v0, float v1, uint32_t& hi, uint32_t& lo) {
    __nv_bfloat16 h0 = __float2bfloat16_rn(v0);
    __nv_bfloat16 h1 = __float2bfloat16_rn(v1);
    __nv_bfloat16 l0 = __float2bfloat16_rn(v0 - __bfloat162float(h0));
    __nv_bfloat16 l1 = __float2bfloat16_rn(v1 - __bfloat162float(h1));
    __nv_bfloat162 hp = __nv_bfloat162(h0, h1), lp = __nv_bfloat162(l0, l1);
    hi = *(uint32_t*)&hp;
    lo = *(uint32_t*)&lp;
}

__device__ __forceinline__ void hmma(float* d, const uint32_t* a, uint32_t b0, uint32_t b1) {
    asm volatile(
        "mma.sync.aligned.m16n8k16.row.col.f32.bf16.bf16.f32 "
        "{%0,%1,%2,%3}, {%4,%5,%6,%7}, {%8,%9}, {%0,%1,%2,%3};"
        : "+f"(d[0]), "+f"(d[1]), "+f"(d[2]), "+f"(d[3])
        : "r"(a[0]), "r"(a[1]), "r"(a[2]), "r"(a[3]), "r"(b0), "r"(b1));
}

__global__ void __launch_bounds__(256, 1) out_mma(const float* __restrict__ x,
                                                  const float* __restrict__ ner,
                                                  const float* __restrict__ nei,
                                                  const float* __restrict__ bre,
                                                  const float* __restrict__ bim,
                                                  float* __restrict__ out) {
    extern __shared__ char smc[];
    uint32_t* wh = (uint32_t*)(smc + SM_WH);
    uint32_t* wl = (uint32_t*)(smc + SM_WL);
    uint32_t* xh = (uint32_t*)(smc + SM_XH);
    uint32_t* xl = (uint32_t*)(smc + SM_XL);
    float* bias = (float*)(smc + SM_BIAS);

    int tid = threadIdx.x;
    int wid = tid >> 5, lane = tid & 31;
    int v = blockIdx.x;

    // ---- fill W (full 128 rows): 2048 items = p(0..31) x ol(0..63) ----
    {
        const float4* ac = g_AC4 + (size_t)v * 4096;
#pragma unroll
        for (int it = 0; it < 8; it++) {
            int idx = tid + it * 256;       // 0..2047
            int p = idx >> 6;               // i-pair 0..31
            int ol = idx & 63;              // o 0..63
            int i0 = p * 2;
            float4 c0 = ac[i0 * 64 + ol];
            float4 c1 = ac[(i0 + 1) * 64 + ol];
            uint32_t r0 = (2 * ol) * SW + p;
            uint32_t r1 = (2 * ol + 1) * SW + p;
            uint32_t hi, lo;
            split_pack(c0.x, c1.x, hi, lo);   wh[r0]      = hi; wl[r0]      = lo;  // Ar
            split_pack(c0.z, c1.z, hi, lo);   wh[r0 + 32] = hi; wl[r0 + 32] = lo;  // Cr
            split_pack(-c0.w, -c1.w, hi, lo); wh[r0 + 64] = hi; wl[r0 + 64] = lo;  // -Ci
            split_pack(c0.y, c1.y, hi, lo);   wh[r1]      = hi; wl[r1]      = lo;  // Ai
            split_pack(c0.w, c1.w, hi, lo);   wh[r1 + 32] = hi; wl[r1 + 32] = lo;  // Ci
            split_pack(c0.z, c1.z, hi, lo);   wh[r1 + 64] = hi; wl[r1 + 64] = lo;  // Cr
        }
    }
    // ---- fill X (once per v): 2048 items = b(0..63) x p(0..31) ----
#pragma unroll
    for (int it = 0; it < 8; it++) {
        int idx = tid + it * 256;
        int b = idx >> 5;
        int p = idx & 31;
        int i0 = p * 2;
        size_t go = ((size_t)b * VV + v) * 64 + i0;
        float2 xv = *(const float2*)&x[go];
        float4 yv = *(const float4*)&g_y[go];
        uint32_t r = b * SW + p;
        uint32_t hi, lo;
        split_pack(xv.x, xv.y, hi, lo); xh[r]      = hi; xl[r]      = lo;
        split_pack(yv.x, yv.z, hi, lo); xh[r + 32] = hi; xl[r + 32] = lo;
        split_pack(yv.y, yv.w, hi, lo); xh[r + 64] = hi; xl[r + 64] = lo;
    }
    // ---- bias: all 128 rows ----
    if (tid < 128) {
        int o = tid >> 1, rei = tid & 1;
        float re = 0.f, im = 0.f;
#pragma unroll
        for (int d = 0; d < 16; d++) {
            float a = ner[v * 16 + d], b2 = nei[v * 16 + d];
            float pr = bre[d * 64 + o], pi = bim[d * 64 + o];
            re += a * pr - b2 * pi;
            im += a * pi + b2 * pr;
        }
        bias[tid] = rei ? im : re;
    }
    __syncthreads();

    // ---- compute: warp (mt, nh): 32 m-rows x 32 n-cols ----
    int gid = lane >> 2, tig = lane & 3;
    int mt = wid & 3, nh = wid >> 2;
    int m0 = mt * 32;
    int n0 = nh * 32;
    float accH[2][4][4] = {}, accL[2][4][4] = {}, accM[2][4][4] = {};

    for (int kc = 0; kc < 12; kc++) {
        int ka = kc * 8 + tig;
        uint32_t ah[2][4], al[2][4];
#pragma unroll
        for (int mm = 0; mm < 2; mm++) {
            int rlo = (m0 + mm * 16 + gid) * SW + ka;
            int rhi = rlo + 8 * SW;
            ah[mm][0] = wh[rlo];     ah[mm][1] = wh[rhi];
            ah[mm][2] = wh[rlo + 4]; ah[mm][3] = wh[rhi + 4];
            al[mm][0] = wl[rlo];     al[mm][1] = wl[rhi];
            al[mm][2] = wl[rlo + 4]; al[mm][3] = wl[rhi + 4];
        }
#pragma unroll
        for (int nt = 0; nt < 4; nt++) {
            int rb = (n0 + nt * 8 + gid) * SW + ka;
            uint32_t bh0 = xh[rb], bh1 = xh[rb + 4];
            uint32_t bl0 = xl[rb], bl1 = xl[rb + 4];
#pragma unroll
            for (int mm = 0; mm < 2; mm++) {
                hmma(accH[mm][nt], ah[mm], bh0, bh1);
                hmma(accL[mm][nt], al[mm], bh0, bh1);
                hmma(accM[mm][nt], ah[mm], bl0, bl1);
            }
        }
    }

    // ---- epilogue ----
#pragma unroll
    for (int mm = 0; mm < 2; mm++) {
        int m_lo = m0 + mm * 16 + gid, m_hi = m_lo + 8;
        float b_lo = bias[m_lo], b_hi = bias[m_hi];
#pragma unroll
        for (int nt = 0; nt < 4; nt++) {
            int b0 = n0 + nt * 8 + 2 * tig;
            size_t o00 = ((size_t)b0 * VV + v) * 128;
            size_t o01 = ((size_t)(b0 + 1) * VV + v) * 128;
            out[o00 + m_lo] = accH[mm][nt][0] + accL[mm][nt][0] + accM[mm][nt][0] + b_lo;
            out[o01 + m_lo] = accH[mm][nt][1] + accL[mm][nt][1] + accM[mm][nt][1] + b_lo;
            out[o00 + m_hi] = accH[mm][nt][2] + accL[mm][nt][2] + accM[mm][nt][2] + b_hi;
            out[o01 + m_hi] = accH[mm][nt][3] + accL[mm][nt][3] + accM[mm][nt][3] + b_hi;
        }
    }
}

extern "C" void kernel_launch(void* const* d_in, const int* in_sizes, int n_in,
                              void* d_out, int out_size) {
    const float* x   = (const float*)d_in[0];
    const float* ner = (const float*)d_in[1];
    const float* nei = (const float*)d_in[2];
    const float* wr  = (const float*)d_in[3];
    const float* wi  = (const float*)d_in[4];
    const float* bre = (const float*)d_in[5];
    const float* bim = (const float*)d_in[6];
    float* out = (float*)d_out;

    cudaFuncSetAttribute(out_mma, cudaFuncAttributeMaxDynamicSharedMemorySize, SM_TOTAL);

    k1_gram_z<<<32 + 2 * BB, 256>>>(x, ner, nei);             // L1
    k2_reduce_y<<<1 + BB * 32, 256>>>(ner, nei);              // L2
    wcomb_kernel<<<dim3(8, 56), 256>>>(ner, nei, wr, wi);     // L3
    out_mma<<<VV, 256, SM_TOTAL>>>(x, ner, nei, bre, bim, out);  // L4 (ncu target)
}